// round 16
// baseline (speedup 1.0000x reference)
#include <cuda_runtime.h>
#include <cuda_fp16.h>
#include <cstdint>

#define K_DIM 4096
#define N_DIM 4096
#define M_DIM 16384
#define NUM_VEC ((N_DIM * K_DIM) / 8)

__device__ __half g_wh[(size_t)N_DIM * K_DIM];   // fp16 q_weight
__device__ __half g_xh[(size_t)M_DIM * K_DIM];   // fp16 x
__device__ int    g_ready[64];                   // per-chunk producer counters

typedef unsigned long long u64;
#define FFMA2(d, a, b, c) \
    asm("fma.rn.f32x2 %0, %1, %2, %3;" : "=l"(d) : "l"(a), "l"(b), "l"(c))
union F2U { float2 f; u64 u; };

// ===========================================================================
// FUSED persistent kernel: chunked prologue production + fp16 GEMM consumer.
// Grid = 148 (1 CTA/SM, all co-resident -> flag protocol is deadlock-free).
// Chunk c = K columns [64c, 64c+64). Producers fill g_wh/g_xh per chunk and
// release g_ready[c]; the GEMM waits (acquire) on chunk c before prefetching
// it, producing pending chunks instead of spinning.
// ===========================================================================
#define BM 128
#define BN 128
#define BK 64
#define SKP 72
#define NKT (K_DIM / BK)                // 64
#define ABYTES (BM * SKP * 2)
#define BBYTES (BN * SKP * 2)
#define STG (ABYTES + BBYTES)
#define SMEM_BYTES (2 * STG)            // 73728
#define NTHR 256
#define NTILES ((M_DIM / BM) * (N_DIM / BN))   // 4096
#define GRID 148
#define WSLICE 32768                    // W vectors per chunk (4096 rows x 8)
#define XSLICE 262144                   // X float4s per chunk (16384 rows x 16)

__device__ __forceinline__ void cp16(uint32_t saddr, const void* g) {
    asm volatile("cp.async.cg.shared.global [%0], [%1], 16;\n" ::"r"(saddr), "l"(g));
}
__device__ __forceinline__ void ldsm4(uint32_t* r, uint32_t addr) {
    asm volatile("ldmatrix.sync.aligned.m8n8.x4.shared.b16 {%0,%1,%2,%3}, [%4];"
                 : "=r"(r[0]), "=r"(r[1]), "=r"(r[2]), "=r"(r[3]) : "r"(addr));
}
__device__ __forceinline__ void hmma(float* c, const uint32_t* a, const uint32_t* b) {
    asm volatile(
        "mma.sync.aligned.m16n8k16.row.col.f32.f16.f16.f32 "
        "{%0,%1,%2,%3}, {%4,%5,%6,%7}, {%8,%9}, {%0,%1,%2,%3};\n"
        : "+f"(c[0]), "+f"(c[1]), "+f"(c[2]), "+f"(c[3])
        : "r"(a[0]), "r"(a[1]), "r"(a[2]), "r"(a[3]), "r"(b[0]), "r"(b[1]));
}
__device__ __forceinline__ int ld_acquire(const int* p) {
    int v;
    asm volatile("ld.acquire.gpu.b32 %0, [%1];" : "=r"(v) : "l"(p));
    return v;
}

__global__ __launch_bounds__(NTHR, 1) void gemm_fused(
    const float* __restrict__ weight, const float* __restrict__ centroids,
    const float* __restrict__ x, const float* __restrict__ bias,
    float* __restrict__ Y) {
    __shared__ float sc[2048];
    __shared__ float scc[256];
    __shared__ float shcc[256];
    __shared__ int s_flag;
    extern __shared__ __half sm[];
    const uint32_t s0 = (uint32_t)__cvta_generic_to_shared(sm);

    const int tid = threadIdx.x;
    const int bx = blockIdx.x;
    const int wid = tid >> 5, lane = tid & 31;
    const int wm = wid >> 2, wn = wid & 3;       // 2x4 warps, warp tile 64x32

    // ---- centroid tables ----
    for (int i = tid; i < 2048; i += NTHR) sc[i] = centroids[i];
    __syncthreads();
    if (tid < 256) {
        float s = 0.f;
#pragma unroll
        for (int j = 0; j < 8; ++j) { float c = sc[tid * 8 + j]; s += c * c; }
        scc[tid] = s;
        shcc[tid] = 0.5f * s;
    }
    __syncthreads();

    // ---- producer: one chunk slice (CTA-collective) ----
    auto produce = [&](int c) {
        // W quantize slice (same arithmetic as round 15)
        const int ws = (bx * WSLICE) / GRID;
        const int we = ((bx + 1) * WSLICE) / GRID;
        for (int i = ws + tid; i < we; i += NTHR) {
            const int r = i >> 3, jj = i & 7;
            const int vec = r * 512 + c * 8 + jj;
            const float4* p = reinterpret_cast<const float4*>(weight + (size_t)vec * 8);
            float4 a4 = p[0], b4 = p[1];
            float w8[8] = {a4.x, a4.y, a4.z, a4.w, b4.x, b4.y, b4.z, b4.w};
            float vv = 0.f;
#pragma unroll
            for (int j = 0; j < 8; ++j) vv += w8[j] * w8[j];
            const float norm = __fsqrt_rn(vv) + 1e-8f;
            u64 np[4];
#pragma unroll
            for (int j = 0; j < 4; ++j) {
                F2U t;
                t.f.x = __fdiv_rn(w8[2 * j], norm);
                t.f.y = __fdiv_rn(w8[2 * j + 1], norm);
                np[j] = t.u;
            }
            float best = -3.402823e38f;
            int bidx = 0;
#pragma unroll 8
            for (int k = 0; k < 256; ++k) {
                const u64* cp = reinterpret_cast<const u64*>(sc + k * 8);
                F2U init; init.f.x = -shcc[k]; init.f.y = 0.f;
                u64 acc2;
                FFMA2(acc2, np[0], cp[0], init.u);
                FFMA2(acc2, np[1], cp[1], acc2);
                FFMA2(acc2, np[2], cp[2], acc2);
                FFMA2(acc2, np[3], cp[3], acc2);
                F2U rr2; rr2.u = acc2;
                const float s = rr2.f.x + rr2.f.y;   // dot(n,c) - cc/2
                if (s > best) { best = s; bidx = k; }
            }
            const float* cb = sc + bidx * 8;
            float cd = 0.f;
#pragma unroll
            for (int j = 0; j < 8; ++j) cd += w8[j] * cb[j];
            const float scale = __fdiv_rn(cd, scc[bidx] + 1e-8f);
            union { __half h[8]; uint4 q; } ph;
#pragma unroll
            for (int j = 0; j < 8; ++j) ph.h[j] = __float2half_rn(cb[j] * scale);
            reinterpret_cast<uint4*>(g_wh)[vec] = ph.q;
        }
        // X convert slice
        const int xs = (bx * XSLICE) / GRID;
        const int xe = ((bx + 1) * XSLICE) / GRID;
        for (int i = xs + tid; i < xe; i += NTHR) {
            const int r = i >> 4, q = i & 15;
            const size_t off = (size_t)r * K_DIM + (size_t)c * 64 + q * 4;
            float4 v = *reinterpret_cast<const float4*>(x + off);
            union { __half2 h2[2]; uint2 u; } pk;
            pk.h2[0] = __floats2half2_rn(v.x, v.y);
            pk.h2[1] = __floats2half2_rn(v.z, v.w);
            *reinterpret_cast<uint2*>(g_xh + off) = pk.u;
        }
        __threadfence();
        __syncthreads();
        if (tid == 0) atomicAdd(&g_ready[c], 1);
    };

    int prod_c = 0;
    auto wait_ready = [&](int c) {
        for (;;) {
            if (tid == 0) s_flag = ld_acquire(&g_ready[c]);
            __syncthreads();
            const int r = s_flag;
            __syncthreads();
            if (r >= GRID) break;
            if (prod_c < NKT) { produce(prod_c); ++prod_c; }
            else __nanosleep(200);
        }
    };

    // ---- bootstrap production (keeps producers 3 chunks ahead) ----
    produce(0); produce(1); produce(2);
    prod_c = 3;
    bool all_done = false;

    // ---- GEMM state ----
    const int t8 = lane >> 3, rr = lane & 7;
    const int a_row = (t8 & 1) * 8 + rr;
    const int a_col = (t8 >> 1) * 8;
    const int b_row = (t8 >> 1) * 8 + rr;
    const int b_col = (t8 & 1) * 8;
    const int a_base_row = wm * 64 + a_row;
    const int b_base_row = wn * 32 + b_row;

    float acc[4][4][4];
#pragma unroll
    for (int i = 0; i < 4; ++i)
#pragma unroll
        for (int j = 0; j < 4; ++j)
#pragma unroll
            for (int r = 0; r < 4; ++r) acc[i][j][r] = 0.f;

    auto load_stage = [&](int st, int tile, int kt) {
        const int m0 = (tile >> 5) * BM;
        const int n0 = (tile & 31) * BN;
        const int k0 = kt * BK;
        const uint32_t sA = s0 + (uint32_t)st * STG;
        const uint32_t sB = sA + ABYTES;
#pragma unroll
        for (int j = 0; j < 4; ++j) {
            const int idx = tid + j * NTHR;
            const int row = idx >> 3, c = idx & 7;
            cp16(sA + (uint32_t)(row * SKP + c * 8) * 2u,
                 g_xh + (size_t)(m0 + row) * K_DIM + k0 + c * 8);
        }
#pragma unroll
        for (int j = 0; j < 4; ++j) {
            const int idx = tid + j * NTHR;
            const int row = idx >> 3, c = idx & 7;
            cp16(sB + (uint32_t)(row * SKP + c * 8) * 2u,
                 g_wh + (size_t)(n0 + row) * K_DIM + k0 + c * 8);
        }
    };

    wait_ready(0);
    int st = 0;
    load_stage(0, bx, 0);
    asm volatile("cp.async.commit_group;\n");

    for (int tile = bx; tile < NTILES; tile += GRID) {
        for (int kt = 0; kt < NKT; ++kt) {
            // keep producing ahead of the pipeline (tile 0 era only)
            if (!all_done && prod_c < NKT) { produce(prod_c); ++prod_c; }

            asm volatile("cp.async.wait_group 0;\n");
            __syncthreads();   // stage st ready; all warps done with st^1

            const bool has_next = (kt + 1 < NKT) || (tile + GRID < NTILES);
            if (has_next) {
                const int ntile = (kt + 1 < NKT) ? tile : tile + GRID;
                const int nkt = (kt + 1 < NKT) ? kt + 1 : 0;
                if (!all_done) {
                    wait_ready(nkt);
                    if (nkt == NKT - 1) all_done = true;  // chunk 63 global -> all ready
                }
                load_stage(st ^ 1, ntile, nkt);
                asm volatile("cp.async.commit_group;\n");
            }

            const uint32_t sA = s0 + (uint32_t)st * STG;
            const uint32_t sB = sA + ABYTES;
#pragma unroll
            for (int ks = 0; ks < 4; ++ks) {
                const int kc = ks * 16;
                uint32_t a[4][4], b[4][2];
#pragma unroll
                for (int i = 0; i < 4; ++i) {
                    const uint32_t off =
                        (uint32_t)((a_base_row + i * 16) * SKP + kc + a_col) * 2u;
                    ldsm4(a[i], sA + off);
                }
#pragma unroll
                for (int p = 0; p < 2; ++p) {
                    const uint32_t off =
                        (uint32_t)((b_base_row + p * 16) * SKP + kc + b_col) * 2u;
                    uint32_t u[4];
                    ldsm4(u, sB + off);
                    b[2 * p][0] = u[0]; b[2 * p][1] = u[1];
                    b[2 * p + 1][0] = u[2]; b[2 * p + 1][1] = u[3];
                }
#pragma unroll
                for (int i = 0; i < 4; ++i)
#pragma unroll
                    for (int j = 0; j < 4; ++j)
                        hmma(acc[i][j], a[i], b[j]);
            }
            st ^= 1;
        }

        // ---- epilogue ----
        {
            const int m0 = (tile >> 5) * BM;
            const int n0 = (tile & 31) * BN;
            const int g = lane >> 2, t = lane & 3;
#pragma unroll
            for (int i = 0; i < 4; ++i) {
#pragma unroll
                for (int j = 0; j < 4; ++j) {
                    const int row = m0 + wm * 64 + i * 16 + g;
                    const int col = n0 + wn * 32 + j * 8 + t * 2;
                    const float b0 = __ldg(&bias[col]);
                    const float b1 = __ldg(&bias[col + 1]);
                    float2 r0 = make_float2(acc[i][j][0] + b0, acc[i][j][1] + b1);
                    float2 r1 = make_float2(acc[i][j][2] + b0, acc[i][j][3] + b1);
                    *reinterpret_cast<float2*>(&Y[(size_t)row * N_DIM + col]) = r0;
                    *reinterpret_cast<float2*>(&Y[(size_t)(row + 8) * N_DIM + col]) = r1;
                    acc[i][j][0] = 0.f; acc[i][j][1] = 0.f;
                    acc[i][j][2] = 0.f; acc[i][j][3] = 0.f;
                }
            }
        }
    }
}

// ===========================================================================
extern "C" void kernel_launch(void* const* d_in, const int* in_sizes, int n_in,
                              void* d_out, int out_size) {
    const float* x = (const float*)d_in[0];
    const float* weight = (const float*)d_in[1];
    const float* bias = (const float*)d_in[2];
    const float* centroids = (const float*)d_in[3];
    float* Y = (float*)d_out;

    // reset chunk-ready counters every call (graph replays included)
    void* pready = nullptr;
    cudaGetSymbolAddress(&pready, g_ready);
    cudaMemsetAsync(pready, 0, 64 * sizeof(int), 0);

    cudaFuncSetAttribute(gemm_fused, cudaFuncAttributeMaxDynamicSharedMemorySize, SMEM_BYTES);
    gemm_fused<<<GRID, NTHR, SMEM_BYTES>>>(weight, centroids, x, bias, Y);
}

// round 17
// speedup vs baseline: 1.4253x; 1.4253x over previous
#include <cuda_runtime.h>
#include <cuda_fp16.h>
#include <cstdint>

#define K_DIM 4096
#define N_DIM 4096
#define M_DIM 16384
#define NUM_VEC ((N_DIM * K_DIM) / 8)

__device__ __half g_wh[(size_t)N_DIM * K_DIM];   // fp16 q_weight
__device__ __half g_xh[(size_t)M_DIM * K_DIM];   // fp16 x

// ===========================================================================
// Kernel 1 (fused prologue):
//   blocks [0, QBLK):         VPTQ quantize weight -> fp16 (2 vec/thread)
//   blocks [QBLK, QBLK+CBLK): x fp32 -> fp16
// Identical arithmetic to the round-12 champion; k-loop unroll deepened to 8
// so 16 independent k-iterations cover the FADD->FSETP->SEL latency chain.
// ===========================================================================
typedef unsigned long long u64;
#define FFMA2(d, a, b, c) \
    asm("fma.rn.f32x2 %0, %1, %2, %3;" : "=l"(d) : "l"(a), "l"(b), "l"(c))
union F2U { float2 f; u64 u; };

#define QBLK (NUM_VEC / 512)                     // 4096 (512 vectors/block)
#define CBLK ((M_DIM * (K_DIM / 4)) / 1024)      // 16384

__global__ __launch_bounds__(256) void prologue(const float* __restrict__ weight,
                                                const float* __restrict__ centroids,
                                                const float* __restrict__ x) {
    const int tid = threadIdx.x;

    if (blockIdx.x >= QBLK) {
        // ---- convert_x: 1024 float4 per block ----
        const size_t base = (size_t)(blockIdx.x - QBLK) * 1024 + tid;
#pragma unroll
        for (int j = 0; j < 4; ++j) {
            const size_t gid = base + (size_t)j * 256;
            float4 v = reinterpret_cast<const float4*>(x)[gid];
            union { __half2 h2[2]; uint2 u; } p;
            p.h2[0] = __floats2half2_rn(v.x, v.y);
            p.h2[1] = __floats2half2_rn(v.z, v.w);
            reinterpret_cast<uint2*>(g_xh)[gid] = p.u;
        }
        return;
    }

    // ---- quantize: 2 vectors/thread ----
    __shared__ float sc[2048];
    __shared__ float scc[256];
    __shared__ float shcc[256];
    for (int i = tid; i < 2048; i += 256) sc[i] = centroids[i];
    __syncthreads();
    if (tid < 256) {
        float s = 0.f;
#pragma unroll
        for (int j = 0; j < 8; ++j) { float c = sc[tid * 8 + j]; s += c * c; }
        scc[tid] = s;
        shcc[tid] = 0.5f * s;
    }
    __syncthreads();

    const int vbase = blockIdx.x * 512 + tid;    // vectors vbase, vbase+256

    u64 np[2][4];
#pragma unroll
    for (int u = 0; u < 2; ++u) {
        const float4* p = reinterpret_cast<const float4*>(weight + (size_t)(vbase + 256 * u) * 8);
        float4 a = p[0], b = p[1];
        float w[8] = {a.x, a.y, a.z, a.w, b.x, b.y, b.z, b.w};
        float vv = 0.f;
#pragma unroll
        for (int j = 0; j < 8; ++j) vv += w[j] * w[j];
        const float norm = __fsqrt_rn(vv) + 1e-8f;
#pragma unroll
        for (int j = 0; j < 4; ++j) {
            F2U t;
            t.f.x = __fdiv_rn(w[2 * j], norm);
            t.f.y = __fdiv_rn(w[2 * j + 1], norm);
            np[u][j] = t.u;
        }
    }

    float best[2] = {-3.402823e38f, -3.402823e38f};
    int bidx[2] = {0, 0};

#pragma unroll 8
    for (int k = 0; k < 256; ++k) {
        const u64* cp = reinterpret_cast<const u64*>(sc + k * 8);
        const u64 c0 = cp[0], c1 = cp[1], c2 = cp[2], c3 = cp[3];
        F2U init; init.f.x = -shcc[k]; init.f.y = 0.f;
        const u64 iu = init.u;
#pragma unroll
        for (int u = 0; u < 2; ++u) {
            u64 acc;
            FFMA2(acc, np[u][0], c0, iu);
            FFMA2(acc, np[u][1], c1, acc);
            FFMA2(acc, np[u][2], c2, acc);
            FFMA2(acc, np[u][3], c3, acc);
            F2U r; r.u = acc;
            const float s = r.f.x + r.f.y;       // dot(n,c) - cc/2
            if (s > best[u]) { best[u] = s; bidx[u] = k; }
        }
    }

#pragma unroll
    for (int u = 0; u < 2; ++u) {
        const int k = bidx[u];
        const float* cb = sc + k * 8;
        const float4* p = reinterpret_cast<const float4*>(weight + (size_t)(vbase + 256 * u) * 8);
        float4 a = p[0], b = p[1];
        const float w[8] = {a.x, a.y, a.z, a.w, b.x, b.y, b.z, b.w};
        float cd = 0.f;
#pragma unroll
        for (int j = 0; j < 8; ++j) cd += w[j] * cb[j];
        const float scale = __fdiv_rn(cd, scc[k] + 1e-8f);
        union { __half h[8]; uint4 q; } ph;
#pragma unroll
        for (int j = 0; j < 8; ++j) ph.h[j] = __float2half_rn(cb[j] * scale);
        reinterpret_cast<uint4*>(g_wh)[vbase + 256 * u] = ph.q;
    }
}

// ===========================================================================
// Kernel 2: PERSISTENT fp16 GEMM (fp32 acc) — round-12 champion, unchanged.
// CTA tile 128x128x64, 2 smem stages, 256 thr (8 warps 2x4, warp tile 64x32),
// 2 CTAs/SM, grid 296.
// ===========================================================================
#define BM 128
#define BN 128
#define BK 64
#define SKP 72
#define NKT (K_DIM / BK)                // 64
#define ABYTES (BM * SKP * 2)
#define BBYTES (BN * SKP * 2)
#define STG (ABYTES + BBYTES)
#define SMEM_BYTES (2 * STG)            // 73728
#define NTHR 256
#define NTILES ((M_DIM / BM) * (N_DIM / BN))   // 4096
#define GRID 296

__device__ __forceinline__ void cp16(uint32_t saddr, const void* g) {
    asm volatile("cp.async.cg.shared.global [%0], [%1], 16;\n" ::"r"(saddr), "l"(g));
}
__device__ __forceinline__ void ldsm4(uint32_t* r, uint32_t addr) {
    asm volatile("ldmatrix.sync.aligned.m8n8.x4.shared.b16 {%0,%1,%2,%3}, [%4];"
                 : "=r"(r[0]), "=r"(r[1]), "=r"(r[2]), "=r"(r[3]) : "r"(addr));
}
__device__ __forceinline__ void hmma(float* c, const uint32_t* a, const uint32_t* b) {
    asm volatile(
        "mma.sync.aligned.m16n8k16.row.col.f32.f16.f16.f32 "
        "{%0,%1,%2,%3}, {%4,%5,%6,%7}, {%8,%9}, {%0,%1,%2,%3};\n"
        : "+f"(c[0]), "+f"(c[1]), "+f"(c[2]), "+f"(c[3])
        : "r"(a[0]), "r"(a[1]), "r"(a[2]), "r"(a[3]), "r"(b[0]), "r"(b[1]));
}

__global__ __launch_bounds__(NTHR, 2) void gemm_f16(const float* __restrict__ bias,
                                                    float* __restrict__ Y) {
    extern __shared__ __half sm[];
    const uint32_t s0 = (uint32_t)__cvta_generic_to_shared(sm);

    const int tid = threadIdx.x;
    const int wid = tid >> 5, lane = tid & 31;
    const int wm = wid >> 2, wn = wid & 3;       // 2x4 warps, warp tile 64x32

    const int t8 = lane >> 3, rr = lane & 7;
    const int a_row = (t8 & 1) * 8 + rr;
    const int a_col = (t8 >> 1) * 8;
    const int b_row = (t8 >> 1) * 8 + rr;
    const int b_col = (t8 & 1) * 8;
    const int a_base_row = wm * 64 + a_row;
    const int b_base_row = wn * 32 + b_row;

    float acc[4][4][4];
#pragma unroll
    for (int i = 0; i < 4; ++i)
#pragma unroll
        for (int j = 0; j < 4; ++j)
#pragma unroll
            for (int r = 0; r < 4; ++r) acc[i][j][r] = 0.f;

    auto load_stage = [&](int st, int tile, int kt) {
        const int m0 = (tile >> 5) * BM;
        const int n0 = (tile & 31) * BN;
        const int k0 = kt * BK;
        const uint32_t sA = s0 + (uint32_t)st * STG;
        const uint32_t sB = sA + ABYTES;
#pragma unroll
        for (int j = 0; j < 4; ++j) {
            const int idx = tid + j * NTHR;
            const int row = idx >> 3, c = idx & 7;
            cp16(sA + (uint32_t)(row * SKP + c * 8) * 2u,
                 g_xh + (size_t)(m0 + row) * K_DIM + k0 + c * 8);
        }
#pragma unroll
        for (int j = 0; j < 4; ++j) {
            const int idx = tid + j * NTHR;
            const int row = idx >> 3, c = idx & 7;
            cp16(sB + (uint32_t)(row * SKP + c * 8) * 2u,
                 g_wh + (size_t)(n0 + row) * K_DIM + k0 + c * 8);
        }
    };

    const int first = blockIdx.x;
    if (first >= NTILES) return;

    int st = 0;
    load_stage(0, first, 0);
    asm volatile("cp.async.commit_group;\n");

    for (int tile = first; tile < NTILES; tile += GRID) {
        for (int kt = 0; kt < NKT; ++kt) {
            asm volatile("cp.async.wait_group 0;\n");
            __syncthreads();   // stage st ready; all warps done with st^1
            if (kt + 1 < NKT) {
                load_stage(st ^ 1, tile, kt + 1);
                asm volatile("cp.async.commit_group;\n");
            } else if (tile + GRID < NTILES) {
                load_stage(st ^ 1, tile + GRID, 0);
                asm volatile("cp.async.commit_group;\n");
            }

            const uint32_t sA = s0 + (uint32_t)st * STG;
            const uint32_t sB = sA + ABYTES;

#pragma unroll
            for (int ks = 0; ks < 4; ++ks) {
                const int kc = ks * 16;
                uint32_t a[4][4], b[4][2];
#pragma unroll
                for (int i = 0; i < 4; ++i) {
                    const uint32_t off =
                        (uint32_t)((a_base_row + i * 16) * SKP + kc + a_col) * 2u;
                    ldsm4(a[i], sA + off);
                }
#pragma unroll
                for (int p = 0; p < 2; ++p) {
                    const uint32_t off =
                        (uint32_t)((b_base_row + p * 16) * SKP + kc + b_col) * 2u;
                    uint32_t u[4];
                    ldsm4(u, sB + off);
                    b[2 * p][0] = u[0]; b[2 * p][1] = u[1];
                    b[2 * p + 1][0] = u[2]; b[2 * p + 1][1] = u[3];
                }
#pragma unroll
                for (int i = 0; i < 4; ++i)
#pragma unroll
                    for (int j = 0; j < 4; ++j)
                        hmma(acc[i][j], a[i], b[j]);
            }
            st ^= 1;
        }

        // ---- epilogue (overlaps next tile's stage-0 prefetch) ----
        {
            const int m0 = (tile >> 5) * BM;
            const int n0 = (tile & 31) * BN;
            const int g = lane >> 2, t = lane & 3;
#pragma unroll
            for (int i = 0; i < 4; ++i) {
#pragma unroll
                for (int j = 0; j < 4; ++j) {
                    const int row = m0 + wm * 64 + i * 16 + g;
                    const int col = n0 + wn * 32 + j * 8 + t * 2;
                    const float b0 = __ldg(&bias[col]);
                    const float b1 = __ldg(&bias[col + 1]);
                    float2 r0 = make_float2(acc[i][j][0] + b0, acc[i][j][1] + b1);
                    float2 r1 = make_float2(acc[i][j][2] + b0, acc[i][j][3] + b1);
                    *reinterpret_cast<float2*>(&Y[(size_t)row * N_DIM + col]) = r0;
                    *reinterpret_cast<float2*>(&Y[(size_t)(row + 8) * N_DIM + col]) = r1;
                    acc[i][j][0] = 0.f; acc[i][j][1] = 0.f;
                    acc[i][j][2] = 0.f; acc[i][j][3] = 0.f;
                }
            }
        }
    }
}

// ===========================================================================
extern "C" void kernel_launch(void* const* d_in, const int* in_sizes, int n_in,
                              void* d_out, int out_size) {
    const float* x = (const float*)d_in[0];
    const float* weight = (const float*)d_in[1];
    const float* bias = (const float*)d_in[2];
    const float* centroids = (const float*)d_in[3];
    float* Y = (float*)d_out;

    prologue<<<QBLK + CBLK, 256>>>(weight, centroids, x);

    cudaFuncSetAttribute(gemm_f16, cudaFuncAttributeMaxDynamicSharedMemorySize, SMEM_BYTES);
    gemm_f16<<<GRID, NTHR, SMEM_BYTES>>>(bias, Y);
}